// round 3
// baseline (speedup 1.0000x reference)
#include <cuda_runtime.h>
#include <cstdint>
#include <math.h>

#define NROWS 4096
#define D     512
#define KCB   8192

// ---------------- scratch (device globals; no allocation) ----------------
__device__ float  g_L[(size_t)NROWS * KCB];   // logits
__device__ float  g_E[(size_t)NROWS * KCB];   // (logit+g)/T, unnormalized
__device__ float  g_c2[KCB];
__device__ float  g_z2[NROWS];
__device__ float  g_lse_p[NROWS];
__device__ float  g_lse_e[NROWS];
__device__ float  g_rowkld[NROWS];
__device__ float  g_avg_partial[8][KCB];
__device__ double g_sq_partial[256];

// ---------------- threefry2x32, key = (0, 42) ----------------
__device__ __forceinline__ void threefry42(uint32_t x0, uint32_t x1,
                                           uint32_t& o0, uint32_t& o1) {
    const uint32_t ks0 = 0u, ks1 = 42u, ks2 = 0x1BD11BDAu ^ 0u ^ 42u;
#define TF_RND(r) { x0 += x1; x1 = (x1 << (r)) | (x1 >> (32 - (r))); x1 ^= x0; }
    x0 += ks0; x1 += ks1;
    TF_RND(13) TF_RND(15) TF_RND(26) TF_RND(6)
    x0 += ks1; x1 += ks2 + 1u;
    TF_RND(17) TF_RND(29) TF_RND(16) TF_RND(24)
    x0 += ks2; x1 += ks0 + 2u;
    TF_RND(13) TF_RND(15) TF_RND(26) TF_RND(6)
    x0 += ks0; x1 += ks1 + 3u;
    TF_RND(17) TF_RND(29) TF_RND(16) TF_RND(24)
    x0 += ks1; x1 += ks2 + 4u;
    TF_RND(13) TF_RND(15) TF_RND(26) TF_RND(6)
    x0 += ks2; x1 += ks0 + 5u;
#undef TF_RND
    o0 = x0; o1 = x1;
}

__device__ __forceinline__ float bits_to_uniform(uint32_t b) {
    // jax: bitcast((bits>>9)|0x3f800000) - 1, then max(0, .)
    float f = __uint_as_float((b >> 9) | 0x3f800000u) - 1.0f;
    return fmaxf(0.0f, f);
}

__device__ __forceinline__ float gumbel_from_u(float u) {
    return -logf(-logf(u + 1e-10f) + 1e-10f);
}

// online-softmax combine: (m,s1,s2) <- merge (m2,s12,s22)
__device__ __forceinline__ void comb(float& m, float& s1, float& s2,
                                     float m2, float s12, float s22) {
    float M = fmaxf(m, m2);
    float a = expf(m - M), b = expf(m2 - M);
    s1 = s1 * a + s12 * b;
    s2 = s2 * a + s22 * b;
    m = M;
}

// ---------------- norms ----------------
__global__ void norms_kernel(const float* __restrict__ z, const float* __restrict__ cb) {
    int row = blockIdx.x;
    const float* src; float* dst;
    if (row < KCB) { src = cb + (size_t)row * D; dst = g_c2 + row; }
    else           { src = z  + (size_t)(row - KCB) * D; dst = g_z2 + (row - KCB); }
    float s = 0.f;
    for (int i = threadIdx.x; i < D; i += 128) { float v = src[i]; s = fmaf(v, v, s); }
    for (int o = 16; o; o >>= 1) s += __shfl_xor_sync(~0u, s, o);
    __shared__ float sm[4];
    if ((threadIdx.x & 31) == 0) sm[threadIdx.x >> 5] = s;
    __syncthreads();
    if (threadIdx.x == 0) *dst = sm[0] + sm[1] + sm[2] + sm[3];
}

// ---------------- GEMM1: logits = -w*(z2 + c2 - 2 zf.cb^T) ----------------
__global__ __launch_bounds__(256) void gemm1_kernel(const float* __restrict__ Z,
                                                    const float* __restrict__ CB,
                                                    const float* __restrict__ varq) {
    __shared__ float As[16][128];
    __shared__ float Bs[16][128];
    int tid = threadIdx.x;
    int m0 = blockIdx.y * 128, n0 = blockIdx.x * 128;
    int lr = tid >> 2;
    int lc = (tid & 3) * 4;
    const float* aptr = Z  + (size_t)(m0 + lr) * D + lc;
    const float* bptr = CB + (size_t)(n0 + lr) * D + lc;
    int ty = tid >> 4, tx = tid & 15;
    float acc[8][8];
#pragma unroll
    for (int i = 0; i < 8; i++)
#pragma unroll
        for (int j = 0; j < 8; j++) acc[i][j] = 0.f;

    for (int k0 = 0; k0 < D; k0 += 16) {
        float4 a0 = *(const float4*)(aptr + k0);
        float4 a1 = *(const float4*)(aptr + k0 + (size_t)64 * D);
        float4 b0 = *(const float4*)(bptr + k0);
        float4 b1 = *(const float4*)(bptr + k0 + (size_t)64 * D);
        As[lc + 0][lr] = a0.x; As[lc + 1][lr] = a0.y; As[lc + 2][lr] = a0.z; As[lc + 3][lr] = a0.w;
        As[lc + 0][lr + 64] = a1.x; As[lc + 1][lr + 64] = a1.y; As[lc + 2][lr + 64] = a1.z; As[lc + 3][lr + 64] = a1.w;
        Bs[lc + 0][lr] = b0.x; Bs[lc + 1][lr] = b0.y; Bs[lc + 2][lr] = b0.z; Bs[lc + 3][lr] = b0.w;
        Bs[lc + 0][lr + 64] = b1.x; Bs[lc + 1][lr + 64] = b1.y; Bs[lc + 2][lr + 64] = b1.z; Bs[lc + 3][lr + 64] = b1.w;
        __syncthreads();
#pragma unroll
        for (int kk = 0; kk < 16; kk++) {
            float ra[8], rb[8];
            *(float4*)(ra)     = *(const float4*)&As[kk][ty * 8];
            *(float4*)(ra + 4) = *(const float4*)&As[kk][ty * 8 + 4];
            *(float4*)(rb)     = *(const float4*)&Bs[kk][tx * 8];
            *(float4*)(rb + 4) = *(const float4*)&Bs[kk][tx * 8 + 4];
#pragma unroll
            for (int i = 0; i < 8; i++)
#pragma unroll
                for (int j = 0; j < 8; j++) acc[i][j] = fmaf(ra[i], rb[j], acc[i][j]);
        }
        __syncthreads();
    }

    float w = 0.5f / fmaxf(varq[0], 1e-10f);
    float cc[8];
#pragma unroll
    for (int j = 0; j < 8; j++) cc[j] = g_c2[n0 + tx * 8 + j];
#pragma unroll
    for (int i = 0; i < 8; i++) {
        int m = m0 + ty * 8 + i;
        float zz = g_z2[m];
        size_t rowoff = (size_t)m * KCB + n0 + tx * 8;
#pragma unroll
        for (int j = 0; j < 8; j++)
            g_L[rowoff + j] = 2.f * w * acc[i][j] - w * (zz + cc[j]);
    }
}

// ---------------- pass C: per-row softmax stats + gumbel ----------------
// JAX threefry_partitionable=True (modern default): element flat index i
// (uint64) -> counter (hi, lo) = (i >> 32, i & 0xffffffff) = (0, i) here,
// 32-bit output = out0 ^ out1.
__global__ __launch_bounds__(256) void passC_kernel() {
    int n = blockIdx.x;           // 0..4095
    size_t base = (size_t)n * KCB;
    int tid = threadIdx.x;

    float mp = -3.4e38f, s1 = 0.f, s2 = 0.f;   // probs: max, sum e, sum e*l
    float me = -3.4e38f, se = 0.f;             // encodings: max, sum e

#pragma unroll 4
    for (int it = 0; it < 32; it++) {
        int k = tid + it * 256;
        float l = g_L[base + k];
        uint32_t lo = (uint32_t)(base + (size_t)k);
        uint32_t o0, o1;
        threefry42(0u, lo, o0, o1);
        float u = bits_to_uniform(o0 ^ o1);
        float e = 2.f * (l + gumbel_from_u(u));
        g_E[base + k] = e;
        // probs stats
        {
            float M = fmaxf(mp, l); float a = expf(mp - M), b = expf(l - M);
            s1 = s1 * a + b; s2 = s2 * a + l * b; mp = M;
        }
        // encoding stats
        {
            float M = fmaxf(me, e); float a = expf(me - M), b = expf(e - M);
            se = se * a + b; me = M;
        }
    }

    // warp reduce
    for (int o = 16; o; o >>= 1) {
        float m2, a2, b2;
        m2 = __shfl_xor_sync(~0u, mp, o); a2 = __shfl_xor_sync(~0u, s1, o); b2 = __shfl_xor_sync(~0u, s2, o);
        comb(mp, s1, s2, m2, a2, b2);
        float d0 = 0.f;
        m2 = __shfl_xor_sync(~0u, me, o); a2 = __shfl_xor_sync(~0u, se, o); b2 = __shfl_xor_sync(~0u, d0, o);
        comb(me, se, d0, m2, a2, b2);
    }

    __shared__ float sm[8][5];
    if ((tid & 31) == 0) {
        int w = tid >> 5;
        sm[w][0] = mp; sm[w][1] = s1; sm[w][2] = s2;
        sm[w][3] = me; sm[w][4] = se;
    }
    __syncthreads();
    if (tid == 0) {
        float Mp = sm[0][0], S1 = sm[0][1], S2 = sm[0][2];
        float Me = sm[0][3], Se = sm[0][4];
        for (int w = 1; w < 8; w++) {
            comb(Mp, S1, S2, sm[w][0], sm[w][1], sm[w][2]);
            float d = 0.f;
            comb(Me, Se, d, sm[w][3], sm[w][4], 0.f);
        }
        float lsep = Mp + logf(S1);
        g_lse_p[n]  = lsep;
        g_rowkld[n] = S2 / S1 - lsep;     // sum_k p*logp for this row
        g_lse_e[n]  = Me + logf(Se);
    }
}

// ---------------- avg_probs partials (column pass over L) ----------------
__global__ __launch_bounds__(256) void avg_kernel() {
    int k = blockIdx.x * 256 + threadIdx.x;
    int c = blockIdx.y;                 // 0..7, chunk of 512 rows
    const float* base = g_L + (size_t)c * 512 * KCB + k;
    const float* lse  = g_lse_p + c * 512;
    float s = 0.f;
#pragma unroll 4
    for (int n = 0; n < 512; n++)
        s += expf(base[(size_t)n * KCB] - lse[n]);
    g_avg_partial[c][k] = s;
}

// ---------------- GEMM2: z_dec = softmax(E) @ codebook, + sq-error partials ----------------
__global__ __launch_bounds__(128) void gemm2_kernel(const float* __restrict__ Z,
                                                    const float* __restrict__ CB,
                                                    float* __restrict__ out) {
    __shared__ float As[16][64];
    __shared__ float Bs[16][128];
    int tid = threadIdx.x;
    int m0 = blockIdx.y * 64, j0 = blockIdx.x * 128;
    int lr = tid >> 2;            // 0..31
    int lc = (tid & 3) * 4;
    float lseA = g_lse_e[m0 + lr];
    float lseB = g_lse_e[m0 + lr + 32];
    const float* aptr = g_E + (size_t)(m0 + lr) * KCB + lc;
    int ty = tid >> 4, tx = tid & 15;   // ty 0..7, tx 0..15
    float acc[8][8];
#pragma unroll
    for (int i = 0; i < 8; i++)
#pragma unroll
        for (int j = 0; j < 8; j++) acc[i][j] = 0.f;

    for (int k0 = 0; k0 < KCB; k0 += 16) {
        float4 a0 = *(const float4*)(aptr + k0);
        float4 a1 = *(const float4*)(aptr + k0 + (size_t)32 * KCB);
        As[lc + 0][lr] = expf(a0.x - lseA);
        As[lc + 1][lr] = expf(a0.y - lseA);
        As[lc + 2][lr] = expf(a0.z - lseA);
        As[lc + 3][lr] = expf(a0.w - lseA);
        As[lc + 0][lr + 32] = expf(a1.x - lseB);
        As[lc + 1][lr + 32] = expf(a1.y - lseB);
        As[lc + 2][lr + 32] = expf(a1.z - lseB);
        As[lc + 3][lr + 32] = expf(a1.w - lseB);
#pragma unroll
        for (int i = 0; i < 4; i++) {
            int idx = tid + 128 * i;
            int r = idx >> 5, c4 = (idx & 31) * 4;
            float4 b = *(const float4*)(CB + (size_t)(k0 + r) * D + j0 + c4);
            *(float4*)&Bs[r][c4] = b;
        }
        __syncthreads();
#pragma unroll
        for (int kk = 0; kk < 16; kk++) {
            float ra[8], rb[8];
            *(float4*)(ra)     = *(const float4*)&As[kk][ty * 8];
            *(float4*)(ra + 4) = *(const float4*)&As[kk][ty * 8 + 4];
            *(float4*)(rb)     = *(const float4*)&Bs[kk][tx * 8];
            *(float4*)(rb + 4) = *(const float4*)&Bs[kk][tx * 8 + 4];
#pragma unroll
            for (int i = 0; i < 8; i++)
#pragma unroll
                for (int j = 0; j < 8; j++) acc[i][j] = fmaf(ra[i], rb[j], acc[i][j]);
        }
        __syncthreads();
    }

    float sq = 0.f;
#pragma unroll
    for (int i = 0; i < 8; i++) {
        int m = m0 + ty * 8 + i;
        size_t rowoff = (size_t)m * D + j0 + tx * 8;
#pragma unroll
        for (int j = 0; j < 8; j++) {
            float v = acc[i][j];
            out[rowoff + j] = v;
            float diff = Z[rowoff + j] - v;
            sq = fmaf(diff, diff, sq);
        }
    }
    for (int o = 16; o; o >>= 1) sq += __shfl_xor_sync(~0u, sq, o);
    __shared__ float ssq[4];
    if ((tid & 31) == 0) ssq[tid >> 5] = sq;
    __syncthreads();
    if (tid == 0)
        g_sq_partial[blockIdx.y * gridDim.x + blockIdx.x] =
            (double)(ssq[0] + ssq[1] + ssq[2] + ssq[3]);
}

// ---------------- finalize: loss + perplexity ----------------
__global__ __launch_bounds__(256) void finalize_kernel(const float* __restrict__ varq,
                                                       float* __restrict__ out) {
    int tid = threadIdx.x;
    double ent = 0.0, kld = 0.0, sq = 0.0;
    for (int k = tid; k < KCB; k += 256) {
        float a = 0.f;
#pragma unroll
        for (int c = 0; c < 8; c++) a += g_avg_partial[c][k];
        a *= (1.0f / (float)NROWS);
        ent += (double)(a * logf(a + 1e-7f));
    }
    for (int r = tid; r < NROWS; r += 256) kld += (double)g_rowkld[r];
    sq = g_sq_partial[tid];
    __shared__ double red[3][256];
    red[0][tid] = ent; red[1][tid] = kld; red[2][tid] = sq;
    __syncthreads();
    for (int o = 128; o; o >>= 1) {
        if (tid < o) {
            red[0][tid] += red[0][tid + o];
            red[1][tid] += red[1][tid + o];
            red[2][tid] += red[2][tid + o];
        }
        __syncthreads();
    }
    if (tid == 0) {
        float w = 0.5f / fmaxf(varq[0], 1e-10f);
        double loss = red[1][0] / 8.0 + (double)w * red[2][0] / 8.0;
        out[(size_t)NROWS * D]     = (float)loss;
        out[(size_t)NROWS * D + 1] = expf(-(float)red[0][0]);
    }
}

// ---------------- launch ----------------
extern "C" void kernel_launch(void* const* d_in, const int* in_sizes, int n_in,
                              void* d_out, int out_size) {
    const float* z    = (const float*)d_in[0];
    const float* varq = (const float*)d_in[1];
    const float* cb   = (const float*)d_in[2];
    float* out = (float*)d_out;

    norms_kernel<<<KCB + NROWS, 128>>>(z, cb);
    dim3 g1(64, 32);
    gemm1_kernel<<<g1, 256>>>(z, cb, varq);
    passC_kernel<<<4096, 256>>>();
    avg_kernel<<<dim3(32, 8), 256>>>();
    dim3 g2(4, 64);
    gemm2_kernel<<<g2, 128>>>(z, cb, out);
    finalize_kernel<<<1, 256>>>(varq, out);
}